// round 10
// baseline (speedup 1.0000x reference)
#include <cuda_runtime.h>
#include <cuda_bf16.h>
#include <cmath>
#include <cstdint>
#include <cstring>
#include <complex>
#include <vector>
#include <algorithm>

typedef unsigned long long ull;

// ============================================================================
// Sizes
// ============================================================================
#define MAXN_AT 16384
#define MAXE_ED 262144
#define MAXNZ   2048
#define SNZ     1280      // smem staging capacity for sparse tables
#define MAXG    96

// ============================================================================
// Consolidated constant tables (single H2D memcpy per replay)
// ============================================================================
struct __align__(16) Tables {
    ulonglong2 self[MAXNZ];   // {meta=(i*32)|(j*32<<16), cv duplicated f32x2}
    int2 tstart[256];         // per p={o*16+si}: {start, end}
    int2 tent[MAXNZ];         // {a, bitcast(v)}
    int2 g[MAXG];             // {(i*32)|(j*32<<16), bitcast(v)}
    int  cs_start[17];
    int  ng, ncs, nct;
};
__device__ Tables dTab;

// ============================================================================
// Device scratch (static; no allocations allowed)
// ============================================================================
__device__ __align__(16) float  g_sh[(size_t)MAXE_ED * 16];
__device__ __align__(16) float  g_basis[(size_t)MAXE_ED * 8];
__device__ int    g_sender[MAXE_ED];
__device__ unsigned char g_live[MAXE_ED];
__device__ int    g_count[MAXN_AT];
__device__ int    g_cursor[MAXN_AT];
__device__ int    g_offsets[MAXN_AT + 1];
__device__ __align__(16) float  g_embedded[(size_t)MAXN_AT * 1024]; // [atom][k(64)][si(16)]
__device__ float  g_embAt[(size_t)MAXN_AT * 16];
__device__ float  g_inv[(size_t)MAXN_AT * 64];
__device__ float  g_atomE[MAXN_AT];

// slot -> l map (compile-time foldable)
__host__ __device__ __forceinline__ constexpr int lof(int s) {
    return s == 0 ? 0 : (s < 4 ? 1 : (s < 9 ? 2 : 3));
}

// ============================================================================
// f32x2 helpers (Blackwell packed fp32; exact IEEE per half)
// ============================================================================
__device__ __forceinline__ ull pk2(float lo, float hi) {
    ull r; asm("mov.b64 %0, {%1, %2};" : "=l"(r) : "f"(lo), "f"(hi)); return r;
}
__device__ __forceinline__ void upk2(ull v, float& lo, float& hi) {
    asm("mov.b64 {%0, %1}, %2;" : "=f"(lo), "=f"(hi) : "l"(v));
}
__device__ __forceinline__ ull fma2(ull a, ull b, ull c) {
    ull r; asm("fma.rn.f32x2 %0, %1, %2, %3;" : "=l"(r) : "l"(a), "l"(b), "l"(c)); return r;
}
__device__ __forceinline__ ull mul2(ull a, ull b) {
    ull r; asm("mul.rn.f32x2 %0, %1, %2;" : "=l"(r) : "l"(a), "l"(b)); return r;
}
#define HALF2 0x3F0000003F000000ULL

// ============================================================================
// Edge geometry
// ============================================================================
__device__ __forceinline__ void edge_geom(const float* pos, int s, int r,
                                          float& d, float& ux, float& uy, float& uz) {
    float dx = __ldg(pos + 3 * r + 0) - __ldg(pos + 3 * s + 0);
    float dy = __ldg(pos + 3 * r + 1) - __ldg(pos + 3 * s + 1);
    float dz = __ldg(pos + 3 * r + 2) - __ldg(pos + 3 * s + 2);
    d = sqrtf(dx * dx + dy * dy + dz * dz + 1e-12f);
    ux = dx / d; uy = dy / d; uz = dz / d;
}

__device__ __forceinline__ void make_sh(float x, float y, float z, float* Y) {
    Y[0] = 0.28209479177387814f;
    const float c1 = 0.4886025119029199f;
    Y[1] = c1 * y; Y[2] = c1 * z; Y[3] = c1 * x;
    Y[4] = 1.0925484305920792f * x * y;
    Y[5] = 1.0925484305920792f * y * z;
    Y[6] = 0.31539156525252005f * (3.0f * z * z - 1.0f);
    Y[7] = 1.0925484305920792f * x * z;
    Y[8] = 0.5462742152960396f * (x * x - y * y);
    Y[9]  = 0.5900435899266435f * y * (3.0f * x * x - y * y);
    Y[10] = 2.890611442640554f * x * y * z;
    Y[11] = 0.4570457994644658f * y * (5.0f * z * z - 1.0f);
    Y[12] = 0.3731763325901154f * z * (5.0f * z * z - 3.0f);
    Y[13] = 0.4570457994644658f * x * (5.0f * z * z - 1.0f);
    Y[14] = 1.445305721320277f * z * (x * x - y * y);
    Y[15] = 0.5900435899266435f * x * (x * x - 3.0f * y * y);
}

__device__ __forceinline__ void make_basis(float d, float* B) {
    float fc = 0.5f * (cosf(3.14159274101257324f * d / 5.0f) + 1.0f);
    #pragma unroll
    for (int i = 0; i < 8; i++) {
        float mu = (float)(5.0 * (double)i / 7.0);
        float t = (d - mu) / 0.625f;
        B[i] = expf(-0.5f * t * t) * fc;
    }
}

// ============================================================================
// Kernel 1: count live edges per receiver (+ expand species embeddings).
// g_count is zeroed by a memset node BEFORE this kernel — no race.
// ============================================================================
__global__ void k_count(const float* __restrict__ pos, const int* __restrict__ snd,
                        const int* __restrict__ rcv, const int* __restrict__ species,
                        const float* __restrict__ emb, int E, int n) {
    int e = blockIdx.x * blockDim.x + threadIdx.x;
    if (e < n) {
        int sp = __ldg(species + e);
        #pragma unroll
        for (int c = 0; c < 16; c++)
            g_embAt[e * 16 + c] = __ldg(emb + sp * 16 + c);
    }
    if (e >= E) return;
    int s = __ldg(snd + e), r = __ldg(rcv + e);
    float dx = __ldg(pos + 3 * r + 0) - __ldg(pos + 3 * s + 0);
    float dy = __ldg(pos + 3 * r + 1) - __ldg(pos + 3 * s + 1);
    float dz = __ldg(pos + 3 * r + 2) - __ldg(pos + 3 * s + 2);
    float d2 = dx * dx + dy * dy + dz * dz + 1e-12f;
    unsigned char live = (d2 < 25.0f) ? 1 : 0;   // flag reused by scatter: always consistent
    g_live[e] = live;
    if (live) atomicAdd(&g_count[r], 1);
}

// ============================================================================
// Kernel 2: exclusive scan (single block)
// ============================================================================
__global__ void k_scan(int n) {
    __shared__ int part[1024];
    int tid = threadIdx.x;
    int chunk = (n + 1023) >> 10;
    int beg = tid * chunk, end = min(beg + chunk, n);
    int s = 0;
    for (int i = beg; i < end; i++) s += g_count[i];
    part[tid] = s;
    __syncthreads();
    for (int off = 1; off < 1024; off <<= 1) {
        int v = (tid >= off) ? part[tid - off] : 0;
        __syncthreads();
        part[tid] += v;
        __syncthreads();
    }
    int run = (tid == 0) ? 0 : part[tid - 1];
    for (int i = beg; i < end; i++) {
        g_offsets[i] = run;
        g_cursor[i] = run;
        run += g_count[i];
    }
    if (tid == 1023) g_offsets[n] = part[1023];
}

// ============================================================================
// Kernel 3: scatter live edges receiver-sorted
// ============================================================================
__global__ void k_scatter(const float* __restrict__ pos, const int* __restrict__ snd,
                          const int* __restrict__ rcv, int E) {
    int e = blockIdx.x * blockDim.x + threadIdx.x;
    if (e >= E) return;
    if (!g_live[e]) return;
    int s = __ldg(snd + e), r = __ldg(rcv + e);
    float d, ux, uy, uz;
    edge_geom(pos, s, r, d, ux, uy, uz);
    int slot = atomicAdd(&g_cursor[r], 1);
    float Y[16]; make_sh(ux, uy, uz, Y);
    float B[8];  make_basis(d, B);
    g_sender[slot] = s;
    float4* o4 = (float4*)(g_sh + (size_t)slot * 16);
    o4[0] = make_float4(Y[0], Y[1], Y[2], Y[3]);
    o4[1] = make_float4(Y[4], Y[5], Y[6], Y[7]);
    o4[2] = make_float4(Y[8], Y[9], Y[10], Y[11]);
    o4[3] = make_float4(Y[12], Y[13], Y[14], Y[15]);
    float4* b4 = (float4*)(g_basis + (size_t)slot * 8);
    b4[0] = make_float4(B[0], B[1], B[2], B[3]);
    b4[1] = make_float4(B[4], B[5], B[6], B[7]);
}

// ============================================================================
// Phase A: first MP + CG self-interaction + embedding mul.
// One warp per atom; lane owns channels (lane, lane+32) as an f32x2 pair.
// Output layout: g_embedded[atom][k][si] (k-major).
// ============================================================================
__global__ __launch_bounds__(128, 4) void k_phaseA(const float* __restrict__ Winv,
                                                   int natoms, int ncs) {
    __shared__ ull sWinv2[64];                 // [n(2)][l*8+b]
    __shared__ __align__(16) ulonglong2 sSelf[SNZ];
    __shared__ __align__(16) ull sS2[4][512];  // per warp: o*32+lane
    for (int i = threadIdx.x; i < 64; i += 128) {
        int n = i >> 5, r = i & 31, l = r >> 3, b = r & 7;
        sWinv2[i] = pk2(__ldg(Winv + l * 32 + b * 4 + n),
                        __ldg(Winv + l * 32 + b * 4 + n + 2));
    }
    int nStage = min(ncs, SNZ);
    for (int i = threadIdx.x; i < nStage; i += 128) sSelf[i] = __ldg(&dTab.self[i]);
    __syncthreads();

    int w = threadIdx.x >> 5, lane = threadIdx.x & 31;
    int a = blockIdx.x * 4 + w;
    if (a >= natoms) return;
    int c0 = lane & 15, n0 = lane >> 4;

    ull fa2[16];
    #pragma unroll
    for (int o = 0; o < 16; o++) fa2[o] = 0ULL;

    int beg = __ldg(&g_offsets[a]), end = __ldg(&g_offsets[a + 1]);
    // prefetch sender + species-embedding (breaks the dependent chain)
    int s = (beg < end) ? __ldg(&g_sender[beg]) : 0;
    float ev = __ldg(&g_embAt[s * 16 + c0]);
    for (int e = beg; e < end; e++) {
        float sh[16];
        {
            const float4* p4 = (const float4*)(g_sh + (size_t)e * 16);
            float4 t;
            t = __ldg(p4 + 0); sh[0] = t.x; sh[1] = t.y; sh[2] = t.z; sh[3] = t.w;
            t = __ldg(p4 + 1); sh[4] = t.x; sh[5] = t.y; sh[6] = t.z; sh[7] = t.w;
            t = __ldg(p4 + 2); sh[8] = t.x; sh[9] = t.y; sh[10] = t.z; sh[11] = t.w;
            t = __ldg(p4 + 3); sh[12] = t.x; sh[13] = t.y; sh[14] = t.z; sh[15] = t.w;
        }
        float B[8];
        {
            const float4* p4 = (const float4*)(g_basis + (size_t)e * 8);
            float4 t;
            t = __ldg(p4 + 0); B[0] = t.x; B[1] = t.y; B[2] = t.z; B[3] = t.w;
            t = __ldg(p4 + 1); B[4] = t.x; B[5] = t.y; B[6] = t.z; B[7] = t.w;
        }
        // prefetch next edge's sender/emb
        int sn = (e + 1 < end) ? __ldg(&g_sender[e + 1]) : 0;
        float evn = __ldg(&g_embAt[sn * 16 + c0]);
        ull ev2 = pk2(ev, ev);
        ull B2[8];
        #pragma unroll
        for (int b = 0; b < 8; b++) B2[b] = pk2(B[b], B[b]);
        ull r2[4];
        #pragma unroll
        for (int l = 0; l < 4; l++) {
            ull acc = 0ULL;
            #pragma unroll
            for (int b = 0; b < 8; b++)
                acc = fma2(B2[b], sWinv2[n0 * 32 + l * 8 + b], acc);
            r2[l] = mul2(acc, ev2);
        }
        #pragma unroll
        for (int o = 0; o < 16; o++)
            fa2[o] = fma2(pk2(sh[o], sh[o]), r2[lof(o)], fa2[o]);
        s = sn; ev = evn;
    }
    #pragma unroll
    for (int o = 0; o < 16; o++) fa2[o] = mul2(fa2[o], HALF2);

    // stage packed feats for bilinear self-interaction
    ull* S = sS2[w];
    #pragma unroll
    for (int o = 0; o < 16; o++) S[o * 32 + lane] = fa2[o];
    __syncwarp();

    float embA = __ldg(&g_embAt[a * 16 + c0]);
    ull emb2 = pk2(embA, embA);
    float lo[16], hi[16];
    #pragma unroll
    for (int o = 0; o < 16; o++) {
        ull v2 = fa2[o];
        int b0 = __ldg(&dTab.cs_start[o]), b1 = __ldg(&dTab.cs_start[o + 1]);
        for (int t = b0; t < b1; t++) {
            ulonglong2 en = (t < nStage) ? sSelf[t] : __ldg(&dTab.self[t]);
            unsigned m = (unsigned)en.x;
            int i32 = m & 0xFFFF, j32 = m >> 16;
            v2 = fma2(en.y, mul2(S[i32 + lane], S[j32 + lane]), v2);
        }
        v2 = mul2(v2, emb2);
        upk2(v2, lo[o], hi[o]);
    }
    // k-major stores
    float4* oa = (float4*)(g_embedded + (size_t)a * 1024 + lane * 16);
    float4* ob = (float4*)(g_embedded + (size_t)a * 1024 + (lane + 32) * 16);
    #pragma unroll
    for (int t = 0; t < 4; t++) {
        oa[t] = make_float4(lo[t * 4], lo[t * 4 + 1], lo[t * 4 + 2], lo[t * 4 + 3]);
        ob[t] = make_float4(hi[t * 4], hi[t * 4 + 1], hi[t * 4 + 2], hi[t * 4 + 3]);
    }
}

// ============================================================================
// Phase B: second MP + invariant contraction.
// One warp per atom; f32x2 packed channels; T duplicated f32x2 in smem.
// ============================================================================
__global__ __launch_bounds__(128, 4) void k_phaseB(const float* __restrict__ Weq,
                                                   int natoms, int nG, int nct) {
    __shared__ ull sWeq2[1024];                  // [L(4)][b(8)][lane(32)] packed (k,k+32)
    __shared__ int2 sTst[256];
    __shared__ int2 sTe[SNZ];
    __shared__ __align__(16) ull sScr[4][512];   // per warp: T pairs (256) / mp stage (512)
    __shared__ float sSh[4][16];
    for (int i = threadIdx.x; i < 1024; i += 128) {
        int L = i >> 8, r = i & 255, b = r >> 5, ln = r & 31;
        sWeq2[i] = pk2(__ldg(Weq + L * 512 + b * 64 + ln),
                       __ldg(Weq + L * 512 + b * 64 + 32 + ln));
    }
    for (int i = threadIdx.x; i < 256; i += 128) sTst[i] = __ldg(&dTab.tstart[i]);
    int nStage = min(nct, SNZ);
    for (int i = threadIdx.x; i < nStage; i += 128) sTe[i] = __ldg(&dTab.tent[i]);
    __syncthreads();

    int w = threadIdx.x >> 5, lane = threadIdx.x & 31;
    int a = blockIdx.x * 4 + w;
    if (a >= natoms) return;
    ull* Tw = sScr[w];
    float* Sh = sSh[w];

    ull m2[16];
    #pragma unroll
    for (int o = 0; o < 16; o++) m2[o] = 0ULL;

    int beg = __ldg(&g_offsets[a]), end = __ldg(&g_offsets[a + 1]);
    int s = (beg < end) ? __ldg(&g_sender[beg]) : 0;
    for (int e = beg; e < end; e++) {
        // neighbor gather (k-major: 8 LDG.128), issued first — consumed last
        const float4* Xa = (const float4*)(g_embedded + (size_t)s * 1024 + lane * 16);
        const float4* Xb = (const float4*)(g_embedded + (size_t)s * 1024 + (lane + 32) * 16);
        float4 xa0 = __ldg(Xa + 0), xa1 = __ldg(Xa + 1), xa2 = __ldg(Xa + 2), xa3 = __ldg(Xa + 3);
        float4 xb0 = __ldg(Xb + 0), xb1 = __ldg(Xb + 1), xb2 = __ldg(Xb + 2), xb3 = __ldg(Xb + 3);
        float B[8];
        {
            const float4* p4 = (const float4*)(g_basis + (size_t)e * 8);
            float4 t;
            t = __ldg(p4 + 0); B[0] = t.x; B[1] = t.y; B[2] = t.z; B[3] = t.w;
            t = __ldg(p4 + 1); B[4] = t.x; B[5] = t.y; B[6] = t.z; B[7] = t.w;
        }
        if (lane < 16) Sh[lane] = __ldg(g_sh + (size_t)e * 16 + lane);
        int sn = (e + 1 < end) ? __ldg(&g_sender[e + 1]) : 0;
        // radial weights (packed)
        ull B2[8];
        #pragma unroll
        for (int b = 0; b < 8; b++) B2[b] = pk2(B[b], B[b]);
        ull q2[4];
        #pragma unroll
        for (int L = 0; L < 4; L++) {
            ull acc = 0ULL;
            #pragma unroll
            for (int b = 0; b < 8; b++)
                acc = fma2(B2[b], sWeq2[L * 256 + b * 32 + lane], acc);
            q2[L] = acc;
        }
        __syncwarp();
        // assemble T (duplicated f32x2 per entry), lane-parallel
        #pragma unroll
        for (int pi = 0; pi < 8; pi++) {
            int p = lane + pi * 32;
            int2 se = sTst[p];
            float v = 0.0f;
            for (int t = se.x; t < se.y; t++) {
                int2 en = (t < nStage) ? sTe[t] : __ldg(&dTab.tent[t]);
                v += __int_as_float(en.y) * Sh[en.x];
            }
            ((float2*)Tw)[p] = make_float2(v, v);
        }
        __syncwarp();
        // pack x
        ull x2[16];
        x2[0] = pk2(xa0.x, xb0.x); x2[1] = pk2(xa0.y, xb0.y);
        x2[2] = pk2(xa0.z, xb0.z); x2[3] = pk2(xa0.w, xb0.w);
        x2[4] = pk2(xa1.x, xb1.x); x2[5] = pk2(xa1.y, xb1.y);
        x2[6] = pk2(xa1.z, xb1.z); x2[7] = pk2(xa1.w, xb1.w);
        x2[8] = pk2(xa2.x, xb2.x); x2[9] = pk2(xa2.y, xb2.y);
        x2[10] = pk2(xa2.z, xb2.z); x2[11] = pk2(xa2.w, xb2.w);
        x2[12] = pk2(xa3.x, xb3.x); x2[13] = pk2(xa3.y, xb3.y);
        x2[14] = pk2(xa3.z, xb3.z); x2[15] = pk2(xa3.w, xb3.w);
        // dense 16x16 contraction (f32x2)
        #pragma unroll
        for (int o = 0; o < 16; o++) {
            ull u = 0ULL;
            const ulonglong2* Trow = (const ulonglong2*)(Tw + o * 16);
            #pragma unroll
            for (int t = 0; t < 8; t++) {
                ulonglong2 tv = Trow[t];
                u = fma2(tv.x, x2[2 * t], u);
                u = fma2(tv.y, x2[2 * t + 1], u);
            }
            m2[o] = fma2(q2[lof(o)], u, m2[o]);
        }
        s = sn;
        __syncwarp();
    }

    // mp = 0.5*m ; stage for invariant contraction
    #pragma unroll
    for (int o = 0; o < 16; o++) Tw[o * 32 + lane] = mul2(m2[o], HALF2);
    __syncwarp();
    ull inv2 = Tw[lane];                         // mp[0][0]
    for (int t = 0; t < nG; t++) {
        int2 en = __ldg(&dTab.g[t]);
        unsigned m = (unsigned)en.x;
        int i32 = m & 0xFFFF, j32 = m >> 16;
        unsigned vb = (unsigned)en.y;
        ull cv2 = ((ull)vb << 32) | vb;
        inv2 = fma2(cv2, mul2(Tw[i32 + lane], Tw[j32 + lane]), inv2);
    }
    float vlo, vhi;
    upk2(inv2, vlo, vhi);
    g_inv[(size_t)a * 64 + lane] = vlo;
    g_inv[(size_t)a * 64 + 32 + lane] = vhi;
}

// ============================================================================
// MLP per atom (one warp per atom)
// ============================================================================
__global__ __launch_bounds__(128) void k_mlp(const float* __restrict__ W1,
                                             const float* __restrict__ W2,
                                             const float* __restrict__ wl,
                                             int natoms) {
    __shared__ float sW1[4096], sW2[4096], sWl[64];
    for (int i = threadIdx.x; i < 4096; i += 128) {
        sW1[i] = __ldg(W1 + i);
        sW2[i] = __ldg(W2 + i);
    }
    if (threadIdx.x < 64) sWl[threadIdx.x] = __ldg(wl + threadIdx.x);
    __syncthreads();

    int w = threadIdx.x >> 5, lane = threadIdx.x & 31;
    int a = blockIdx.x * 4 + w;
    if (a >= natoms) return;

    float i0 = g_inv[(size_t)a * 64 + lane];
    float i1 = g_inv[(size_t)a * 64 + 32 + lane];
    float h0 = 0.0f, h1 = 0.0f;
    #pragma unroll
    for (int j = 0; j < 64; j++) {
        float bj = __shfl_sync(0xffffffffu, (j < 32) ? i0 : i1, j & 31);
        h0 += bj * sW1[j * 64 + lane];
        h1 += bj * sW1[j * 64 + 32 + lane];
    }
    h0 = h0 / (1.0f + expf(-h0));
    h1 = h1 / (1.0f + expf(-h1));
    float g0 = 0.0f, g1 = 0.0f;
    #pragma unroll
    for (int j = 0; j < 64; j++) {
        float bj = __shfl_sync(0xffffffffu, (j < 32) ? h0 : h1, j & 31);
        g0 += bj * sW2[j * 64 + lane];
        g1 += bj * sW2[j * 64 + 32 + lane];
    }
    g0 = g0 / (1.0f + expf(-g0));
    g1 = g1 / (1.0f + expf(-g1));
    float p = g0 * sWl[lane] + g1 * sWl[32 + lane];
    #pragma unroll
    for (int off = 16; off; off >>= 1) p += __shfl_xor_sync(0xffffffffu, p, off);
    if (lane == 0) g_atomE[a] = p;
}

__global__ void k_reduce(float* __restrict__ out, int n) {
    __shared__ double sred[1024];
    double s = 0.0;
    for (int i = threadIdx.x; i < n; i += 1024) s += (double)g_atomE[i];
    sred[threadIdx.x] = s;
    __syncthreads();
    for (int st = 512; st; st >>= 1) {
        if (threadIdx.x < st) sred[threadIdx.x] += sred[threadIdx.x + st];
        __syncthreads();
    }
    if (threadIdx.x == 0) out[0] = (float)sred[0];
}

// ============================================================================
// Host: exact port of the reference Clebsch-Gordan / real-SH coupling tables
// ============================================================================
namespace phace_host {

using cd = std::complex<double>;

static double hfact(int n) { double r = 1; for (int i = 2; i <= n; i++) r *= i; return r; }

static double hcg(int j1, int m1, int j2, int m2, int J, int M) {
    if (m1 + m2 != M || J < std::abs(j1 - j2) || J > j1 + j2) return 0.0;
    double pref = std::sqrt((2 * J + 1) * hfact(J + j1 - j2) * hfact(J - j1 + j2) *
                            hfact(j1 + j2 - J) / hfact(j1 + j2 + J + 1));
    pref *= std::sqrt(hfact(J + M) * hfact(J - M) * hfact(j1 - m1) * hfact(j1 + m1) *
                      hfact(j2 - m2) * hfact(j2 + m2));
    double s = 0.0;
    for (int k = 0; k <= j1 + j2 - J; k++) {
        int d0 = k, d1 = j1 + j2 - J - k, d2 = j1 - m1 - k, d3 = j2 + m2 - k;
        int d4 = J - j2 + m1 + k, d5 = J - j1 - m2 + k;
        if (d0 < 0 || d1 < 0 || d2 < 0 || d3 < 0 || d4 < 0 || d5 < 0) continue;
        double den = hfact(d0) * hfact(d1) * hfact(d2) * hfact(d3) * hfact(d4) * hfact(d5);
        s += ((k & 1) ? -1.0 : 1.0) / den;
    }
    return pref * s;
}

static void hureal(int l, cd U[7][7]) {
    for (int i = 0; i < 7; i++)
        for (int j = 0; j < 7; j++) U[i][j] = cd(0.0, 0.0);
    U[l][l] = cd(1.0, 0.0);
    const double is2 = 1.0 / std::sqrt(2.0);
    for (int m = 1; m <= l; m++) {
        double sg = (m & 1) ? -1.0 : 1.0;
        U[l + m][l + m] = cd(sg * is2, 0.0);
        U[l + m][l - m] = cd(is2, 0.0);
        U[l - m][l - m] = cd(0.0, is2);
        U[l - m][l + m] = cd(0.0, -is2 * sg);
    }
}

static void hrealcg(int l1, int l2, int L, float out[7][7][7]) {
    cd U1[7][7], U2[7][7], U3[7][7];
    hureal(l1, U1); hureal(l2, U2); hureal(L, U3);
    int d1 = 2 * l1 + 1, d2 = 2 * l2 + 1, d3 = 2 * L + 1;
    static cd T[7][7][7];
    double sre = 0.0, sim = 0.0;
    for (int a = 0; a < d1; a++)
        for (int b = 0; b < d2; b++)
            for (int c = 0; c < d3; c++) {
                cd acc(0.0, 0.0);
                for (int m = 0; m < d1; m++) {
                    cd u1 = U1[a][m];
                    if (u1.real() == 0.0 && u1.imag() == 0.0) continue;
                    for (int n = 0; n < d2; n++) {
                        cd u2 = U2[b][n];
                        if (u2.real() == 0.0 && u2.imag() == 0.0) continue;
                        for (int o = 0; o < d3; o++) {
                            cd u3 = std::conj(U3[c][o]);
                            if (u3.real() == 0.0 && u3.imag() == 0.0) continue;
                            double cgv = hcg(l1, m - l1, l2, n - l2, L, o - L);
                            if (cgv != 0.0) acc += u1 * u2 * u3 * cgv;
                        }
                    }
                }
                T[a][b][c] = acc;
                sre += std::abs(acc.real());
                sim += std::abs(acc.imag());
            }
    bool usere = (sre >= sim);
    for (int a = 0; a < d1; a++)
        for (int b = 0; b < d2; b++)
            for (int c = 0; c < d3; c++)
                out[a][b][c] = (float)(usere ? T[a][b][c].real() : T[a][b][c].imag());
}

static int f2i(float v) { int r; std::memcpy(&r, &v, 4); return r; }
static unsigned long long fdup(float v) {
    unsigned u; std::memcpy(&u, &v, 4);
    return ((unsigned long long)u << 32) | u;
}

static void build_tables(Tables& H) {
    const int OFF[4] = {0, 1, 4, 9};
    struct E3 { short i, j; float v; };
    struct E2 { short a; float v; };
    std::vector<E3> so[16];
    std::vector<E2> tp[256];
    H.ng = 0;
    static float C[7][7][7];
    for (int l1 = 0; l1 < 4; l1++)
        for (int l2 = 0; l2 < 4; l2++) {
            int Llo = std::abs(l1 - l2), Lhi = std::min(l1 + l2, 3);
            for (int L = Llo; L <= Lhi; L++) {
                hrealcg(l1, l2, L, C);
                for (int a = 0; a < 2 * l1 + 1; a++)
                    for (int b = 0; b < 2 * l2 + 1; b++)
                        for (int c = 0; c < 2 * L + 1; c++) {
                            float v = C[a][b][c];
                            if (std::fabs(v) < 1e-7f) continue;
                            int o = OFF[L] + c, si = OFF[l2] + b, sa = OFF[l1] + a;
                            so[o].push_back({(short)sa, (short)si, v});
                            tp[o * 16 + si].push_back({(short)sa, v});
                            if (L == 0 && l1 == l2 && H.ng < MAXG) {
                                H.g[H.ng].x = (sa * 32) | ((si * 32) << 16);
                                H.g[H.ng].y = f2i(v);
                                H.ng++;
                            }
                        }
            }
        }
    int idx = 0;
    for (int o = 0; o < 16; o++) {
        H.cs_start[o] = idx;
        for (auto& e : so[o]) {
            if (idx >= MAXNZ) break;              // MAXNZ=2048: never hit
            H.self[idx].x = (unsigned long long)((e.i * 32) | ((e.j * 32) << 16));
            H.self[idx].y = fdup(e.v);
            idx++;
        }
    }
    H.cs_start[16] = idx; H.ncs = idx;
    idx = 0;
    for (int p = 0; p < 256; p++) {
        H.tstart[p].x = idx;
        for (auto& e : tp[p]) {
            if (idx >= MAXNZ) break;
            H.tent[idx].x = e.a;
            H.tent[idx].y = f2i(e.v);
            idx++;
        }
        H.tstart[p].y = idx;
    }
    H.nct = idx;
}

} // namespace phace_host

// ============================================================================
// kernel_launch
// ============================================================================
extern "C" void kernel_launch(void* const* d_in, const int* in_sizes, int n_in,
                              void* d_out, int out_size) {
    const float* pos     = (const float*)d_in[0];
    const float* emb     = (const float*)d_in[1];
    const float* Winv    = (const float*)d_in[2];
    const float* Weq     = (const float*)d_in[3];
    const float* W1      = (const float*)d_in[4];
    const float* W2      = (const float*)d_in[5];
    const float* wl      = (const float*)d_in[6];
    const int*   species = (const int*)d_in[7];
    const int*   snd     = (const int*)d_in[8];
    const int*   rcv     = (const int*)d_in[9];
    int N = in_sizes[7];
    int E = in_sizes[8];
    if (N > MAXN_AT) N = MAXN_AT;
    if (E > MAXE_ED) E = MAXE_ED;

    static Tables H;                   // static: source must persist for graph replays
    phace_host::build_tables(H);       // deterministic, rebuilt every call

    // single consolidated upload (one memcpy node)
    cudaMemcpyToSymbolAsync(dTab, &H, sizeof(Tables), 0, cudaMemcpyHostToDevice, 0);

    // zero per-receiver counts via memset node (graph-legal; precedes k_count)
    void* cntPtr = nullptr;
    cudaGetSymbolAddress(&cntPtr, g_count);
    cudaMemsetAsync(cntPtr, 0, (size_t)N * sizeof(int), 0);

    int G = ((E > N ? E : N) + 255) / 256;
    k_count<<<G, 256>>>(pos, snd, rcv, species, emb, E, N);
    k_scan<<<1, 1024>>>(N);
    k_scatter<<<(E + 255) / 256, 256>>>(pos, snd, rcv, E);
    k_phaseA<<<(N + 3) / 4, 128>>>(Winv, N, H.ncs);
    k_phaseB<<<(N + 3) / 4, 128>>>(Weq, N, H.ng, H.nct);
    k_mlp<<<(N + 3) / 4, 128>>>(W1, W2, wl, N);
    k_reduce<<<1, 1024>>>((float*)d_out, N);
}

// round 11
// speedup vs baseline: 1.4926x; 1.4926x over previous
#include <cuda_runtime.h>
#include <cuda_bf16.h>
#include <cmath>
#include <cstdint>
#include <cstring>
#include <complex>
#include <vector>
#include <algorithm>

typedef unsigned long long ull;

// ============================================================================
// Sizes
// ============================================================================
#define MAXN_AT 16384
#define MAXE_ED 262144
#define MAXNZ   2048
#define MAXG    160

// ============================================================================
// Consolidated constant tables (single H2D memcpy per replay)
// ============================================================================
struct __align__(16) Tables {
    ulonglong2 self[MAXNZ];   // merged i<=j: {meta=(i*32)|(j*32<<16), cv dup f32x2}
    int2 tstart[256];         // per p={o*16+si}: {start, end}
    int2 tent[MAXNZ];         // {a, bitcast(v)}
    int2 g[MAXG];             // merged: {(i*32)|(j*32<<16), bitcast(v)}
    int  cs_start[17];
    int  ng, ncs, nct;
};
__device__ Tables dTab;

// ============================================================================
// Device scratch (static; no allocations allowed)
// ============================================================================
__device__ __align__(16) float  g_sh[(size_t)MAXE_ED * 16];
__device__ __align__(16) float  g_basis[(size_t)MAXE_ED * 8];
__device__ int    g_sender[MAXE_ED];
__device__ unsigned char g_live[MAXE_ED];
__device__ int    g_count[MAXN_AT];
__device__ int    g_cursor[MAXN_AT];
__device__ int    g_offsets[MAXN_AT + 1];
__device__ __align__(16) float  g_embedded[(size_t)MAXN_AT * 1024]; // [atom][k(64)][si(16)]
__device__ float  g_embAt[(size_t)MAXN_AT * 16];
__device__ float  g_inv[(size_t)MAXN_AT * 64];
__device__ float  g_atomE[MAXN_AT];

// slot -> l map (compile-time foldable)
__host__ __device__ __forceinline__ constexpr int lof(int s) {
    return s == 0 ? 0 : (s < 4 ? 1 : (s < 9 ? 2 : 3));
}

// ============================================================================
// f32x2 helpers (Blackwell packed fp32; exact IEEE per half)
// ============================================================================
__device__ __forceinline__ ull pk2(float lo, float hi) {
    ull r; asm("mov.b64 %0, {%1, %2};" : "=l"(r) : "f"(lo), "f"(hi)); return r;
}
__device__ __forceinline__ void upk2(ull v, float& lo, float& hi) {
    asm("mov.b64 {%0, %1}, %2;" : "=f"(lo), "=f"(hi) : "l"(v));
}
__device__ __forceinline__ ull fma2(ull a, ull b, ull c) {
    ull r; asm("fma.rn.f32x2 %0, %1, %2, %3;" : "=l"(r) : "l"(a), "l"(b), "l"(c)); return r;
}
__device__ __forceinline__ ull mul2(ull a, ull b) {
    ull r; asm("mul.rn.f32x2 %0, %1, %2;" : "=l"(r) : "l"(a), "l"(b)); return r;
}
#define HALF2 0x3F0000003F000000ULL

// ============================================================================
// Edge geometry
// ============================================================================
__device__ __forceinline__ void edge_geom(const float* pos, int s, int r,
                                          float& d, float& ux, float& uy, float& uz) {
    float dx = __ldg(pos + 3 * r + 0) - __ldg(pos + 3 * s + 0);
    float dy = __ldg(pos + 3 * r + 1) - __ldg(pos + 3 * s + 1);
    float dz = __ldg(pos + 3 * r + 2) - __ldg(pos + 3 * s + 2);
    d = sqrtf(dx * dx + dy * dy + dz * dz + 1e-12f);
    ux = dx / d; uy = dy / d; uz = dz / d;
}

__device__ __forceinline__ void make_sh(float x, float y, float z, float* Y) {
    Y[0] = 0.28209479177387814f;
    const float c1 = 0.4886025119029199f;
    Y[1] = c1 * y; Y[2] = c1 * z; Y[3] = c1 * x;
    Y[4] = 1.0925484305920792f * x * y;
    Y[5] = 1.0925484305920792f * y * z;
    Y[6] = 0.31539156525252005f * (3.0f * z * z - 1.0f);
    Y[7] = 1.0925484305920792f * x * z;
    Y[8] = 0.5462742152960396f * (x * x - y * y);
    Y[9]  = 0.5900435899266435f * y * (3.0f * x * x - y * y);
    Y[10] = 2.890611442640554f * x * y * z;
    Y[11] = 0.4570457994644658f * y * (5.0f * z * z - 1.0f);
    Y[12] = 0.3731763325901154f * z * (5.0f * z * z - 3.0f);
    Y[13] = 0.4570457994644658f * x * (5.0f * z * z - 1.0f);
    Y[14] = 1.445305721320277f * z * (x * x - y * y);
    Y[15] = 0.5900435899266435f * x * (x * x - 3.0f * y * y);
}

__device__ __forceinline__ void make_basis(float d, float* B) {
    float fc = 0.5f * (cosf(3.14159274101257324f * d / 5.0f) + 1.0f);
    #pragma unroll
    for (int i = 0; i < 8; i++) {
        float mu = (float)(5.0 * (double)i / 7.0);
        float t = (d - mu) / 0.625f;
        B[i] = expf(-0.5f * t * t) * fc;
    }
}

// ============================================================================
// Kernel 1: count live edges per receiver (+ expand species embeddings).
// g_count is zeroed by a memset node BEFORE this kernel — no race.
// ============================================================================
__global__ void k_count(const float* __restrict__ pos, const int* __restrict__ snd,
                        const int* __restrict__ rcv, const int* __restrict__ species,
                        const float* __restrict__ emb, int E, int n) {
    int e = blockIdx.x * blockDim.x + threadIdx.x;
    if (e < n) {
        int sp = __ldg(species + e);
        #pragma unroll
        for (int c = 0; c < 16; c++)
            g_embAt[e * 16 + c] = __ldg(emb + sp * 16 + c);
    }
    if (e >= E) return;
    int s = __ldg(snd + e), r = __ldg(rcv + e);
    float dx = __ldg(pos + 3 * r + 0) - __ldg(pos + 3 * s + 0);
    float dy = __ldg(pos + 3 * r + 1) - __ldg(pos + 3 * s + 1);
    float dz = __ldg(pos + 3 * r + 2) - __ldg(pos + 3 * s + 2);
    float d2 = dx * dx + dy * dy + dz * dz + 1e-12f;
    unsigned char live = (d2 < 25.0f) ? 1 : 0;   // flag reused by scatter: always consistent
    g_live[e] = live;
    if (live) atomicAdd(&g_count[r], 1);
}

// ============================================================================
// Kernel 2: exclusive scan (single block)
// ============================================================================
__global__ void k_scan(int n) {
    __shared__ int part[1024];
    int tid = threadIdx.x;
    int chunk = (n + 1023) >> 10;
    int beg = tid * chunk, end = min(beg + chunk, n);
    int s = 0;
    for (int i = beg; i < end; i++) s += g_count[i];
    part[tid] = s;
    __syncthreads();
    for (int off = 1; off < 1024; off <<= 1) {
        int v = (tid >= off) ? part[tid - off] : 0;
        __syncthreads();
        part[tid] += v;
        __syncthreads();
    }
    int run = (tid == 0) ? 0 : part[tid - 1];
    for (int i = beg; i < end; i++) {
        g_offsets[i] = run;
        g_cursor[i] = run;
        run += g_count[i];
    }
    if (tid == 1023) g_offsets[n] = part[1023];
}

// ============================================================================
// Kernel 3: scatter live edges receiver-sorted
// ============================================================================
__global__ void k_scatter(const float* __restrict__ pos, const int* __restrict__ snd,
                          const int* __restrict__ rcv, int E) {
    int e = blockIdx.x * blockDim.x + threadIdx.x;
    if (e >= E) return;
    if (!g_live[e]) return;
    int s = __ldg(snd + e), r = __ldg(rcv + e);
    float d, ux, uy, uz;
    edge_geom(pos, s, r, d, ux, uy, uz);
    int slot = atomicAdd(&g_cursor[r], 1);
    float Y[16]; make_sh(ux, uy, uz, Y);
    float B[8];  make_basis(d, B);
    g_sender[slot] = s;
    float4* o4 = (float4*)(g_sh + (size_t)slot * 16);
    o4[0] = make_float4(Y[0], Y[1], Y[2], Y[3]);
    o4[1] = make_float4(Y[4], Y[5], Y[6], Y[7]);
    o4[2] = make_float4(Y[8], Y[9], Y[10], Y[11]);
    o4[3] = make_float4(Y[12], Y[13], Y[14], Y[15]);
    float4* b4 = (float4*)(g_basis + (size_t)slot * 8);
    b4[0] = make_float4(B[0], B[1], B[2], B[3]);
    b4[1] = make_float4(B[4], B[5], B[6], B[7]);
}

// ============================================================================
// Phase A: first MP + CG self-interaction (symmetric-merged) + embedding mul.
// One warp per atom; lane owns channels (lane, lane+32) as an f32x2 pair.
// Output layout: g_embedded[atom][k][si] (k-major).
// ============================================================================
__global__ __launch_bounds__(128, 4) void k_phaseA(const float* __restrict__ Winv,
                                                   int natoms) {
    __shared__ ull sWinv2[64];                 // [n(2)][l*8+b]
    __shared__ __align__(16) ull sS2[4][512];  // per warp: o*32+lane
    for (int i = threadIdx.x; i < 64; i += 128) {
        int n = i >> 5, r = i & 31, l = r >> 3, b = r & 7;
        sWinv2[i] = pk2(__ldg(Winv + l * 32 + b * 4 + n),
                        __ldg(Winv + l * 32 + b * 4 + n + 2));
    }
    __syncthreads();

    int w = threadIdx.x >> 5, lane = threadIdx.x & 31;
    int a = blockIdx.x * 4 + w;
    if (a >= natoms) return;
    int c0 = lane & 15, n0 = lane >> 4;

    ull fa2[16];
    #pragma unroll
    for (int o = 0; o < 16; o++) fa2[o] = 0ULL;

    int beg = __ldg(&g_offsets[a]), end = __ldg(&g_offsets[a + 1]);
    int s = (beg < end) ? __ldg(&g_sender[beg]) : 0;
    float ev = __ldg(&g_embAt[s * 16 + c0]);
    for (int e = beg; e < end; e++) {
        float sh[16];
        {
            const float4* p4 = (const float4*)(g_sh + (size_t)e * 16);
            float4 t;
            t = __ldg(p4 + 0); sh[0] = t.x; sh[1] = t.y; sh[2] = t.z; sh[3] = t.w;
            t = __ldg(p4 + 1); sh[4] = t.x; sh[5] = t.y; sh[6] = t.z; sh[7] = t.w;
            t = __ldg(p4 + 2); sh[8] = t.x; sh[9] = t.y; sh[10] = t.z; sh[11] = t.w;
            t = __ldg(p4 + 3); sh[12] = t.x; sh[13] = t.y; sh[14] = t.z; sh[15] = t.w;
        }
        float B[8];
        {
            const float4* p4 = (const float4*)(g_basis + (size_t)e * 8);
            float4 t;
            t = __ldg(p4 + 0); B[0] = t.x; B[1] = t.y; B[2] = t.z; B[3] = t.w;
            t = __ldg(p4 + 1); B[4] = t.x; B[5] = t.y; B[6] = t.z; B[7] = t.w;
        }
        int sn = (e + 1 < end) ? __ldg(&g_sender[e + 1]) : 0;
        float evn = __ldg(&g_embAt[sn * 16 + c0]);
        ull ev2 = pk2(ev, ev);
        ull B2[8];
        #pragma unroll
        for (int b = 0; b < 8; b++) B2[b] = pk2(B[b], B[b]);
        ull r2[4];
        #pragma unroll
        for (int l = 0; l < 4; l++) {
            ull acc = 0ULL;
            #pragma unroll
            for (int b = 0; b < 8; b++)
                acc = fma2(B2[b], sWinv2[n0 * 32 + l * 8 + b], acc);
            r2[l] = mul2(acc, ev2);
        }
        #pragma unroll
        for (int o = 0; o < 16; o++)
            fa2[o] = fma2(pk2(sh[o], sh[o]), r2[lof(o)], fa2[o]);
        s = sn; ev = evn;
    }
    #pragma unroll
    for (int o = 0; o < 16; o++) fa2[o] = mul2(fa2[o], HALF2);

    // stage packed feats for bilinear self-interaction
    ull* S = sS2[w];
    #pragma unroll
    for (int o = 0; o < 16; o++) S[o * 32 + lane] = fa2[o];
    __syncwarp();

    float embA = __ldg(&g_embAt[a * 16 + c0]);
    ull emb2 = pk2(embA, embA);
    float lo[16], hi[16];
    #pragma unroll
    for (int o = 0; o < 16; o++) {
        ull v2 = fa2[o];
        int b0 = __ldg(&dTab.cs_start[o]), b1 = __ldg(&dTab.cs_start[o + 1]);
        for (int t = b0; t < b1; t++) {
            ulonglong2 en = __ldg(&dTab.self[t]);
            unsigned m = (unsigned)en.x;
            int i32 = m & 0xFFFF, j32 = m >> 16;
            v2 = fma2(en.y, mul2(S[i32 + lane], S[j32 + lane]), v2);
        }
        v2 = mul2(v2, emb2);
        upk2(v2, lo[o], hi[o]);
    }
    // k-major stores
    float4* oa = (float4*)(g_embedded + (size_t)a * 1024 + lane * 16);
    float4* ob = (float4*)(g_embedded + (size_t)a * 1024 + (lane + 32) * 16);
    #pragma unroll
    for (int t = 0; t < 4; t++) {
        oa[t] = make_float4(lo[t * 4], lo[t * 4 + 1], lo[t * 4 + 2], lo[t * 4 + 3]);
        ob[t] = make_float4(hi[t * 4], hi[t * 4 + 1], hi[t * 4 + 2], hi[t * 4 + 3]);
    }
}

// ============================================================================
// Phase B: second MP + invariant contraction (merged g table).
// One warp per atom; f32x2 packed channels; T duplicated f32x2 in smem.
// ============================================================================
__global__ __launch_bounds__(128, 4) void k_phaseB(const float* __restrict__ Weq,
                                                   int natoms, int nG) {
    __shared__ ull sWeq2[1024];                  // [L(4)][b(8)][lane(32)] packed (k,k+32)
    __shared__ __align__(16) ull sScr[4][512];   // per warp: T pairs (256) / mp stage (512)
    __shared__ float sSh[4][16];
    for (int i = threadIdx.x; i < 1024; i += 128) {
        int L = i >> 8, r = i & 255, b = r >> 5, ln = r & 31;
        sWeq2[i] = pk2(__ldg(Weq + L * 512 + b * 64 + ln),
                       __ldg(Weq + L * 512 + b * 64 + 32 + ln));
    }
    __syncthreads();

    int w = threadIdx.x >> 5, lane = threadIdx.x & 31;
    int a = blockIdx.x * 4 + w;
    if (a >= natoms) return;
    ull* Tw = sScr[w];
    float* Sh = sSh[w];

    ull m2[16];
    #pragma unroll
    for (int o = 0; o < 16; o++) m2[o] = 0ULL;

    int beg = __ldg(&g_offsets[a]), end = __ldg(&g_offsets[a + 1]);
    int s = (beg < end) ? __ldg(&g_sender[beg]) : 0;
    for (int e = beg; e < end; e++) {
        // neighbor gather (k-major: 8 LDG.128), issued first — consumed last
        const float4* Xa = (const float4*)(g_embedded + (size_t)s * 1024 + lane * 16);
        const float4* Xb = (const float4*)(g_embedded + (size_t)s * 1024 + (lane + 32) * 16);
        float4 xa0 = __ldg(Xa + 0), xa1 = __ldg(Xa + 1), xa2 = __ldg(Xa + 2), xa3 = __ldg(Xa + 3);
        float4 xb0 = __ldg(Xb + 0), xb1 = __ldg(Xb + 1), xb2 = __ldg(Xb + 2), xb3 = __ldg(Xb + 3);
        float B[8];
        {
            const float4* p4 = (const float4*)(g_basis + (size_t)e * 8);
            float4 t;
            t = __ldg(p4 + 0); B[0] = t.x; B[1] = t.y; B[2] = t.z; B[3] = t.w;
            t = __ldg(p4 + 1); B[4] = t.x; B[5] = t.y; B[6] = t.z; B[7] = t.w;
        }
        if (lane < 16) Sh[lane] = __ldg(g_sh + (size_t)e * 16 + lane);
        int sn = (e + 1 < end) ? __ldg(&g_sender[e + 1]) : 0;
        // radial weights (packed)
        ull B2[8];
        #pragma unroll
        for (int b = 0; b < 8; b++) B2[b] = pk2(B[b], B[b]);
        ull q2[4];
        #pragma unroll
        for (int L = 0; L < 4; L++) {
            ull acc = 0ULL;
            #pragma unroll
            for (int b = 0; b < 8; b++)
                acc = fma2(B2[b], sWeq2[L * 256 + b * 32 + lane], acc);
            q2[L] = acc;
        }
        __syncwarp();
        // assemble T (duplicated f32x2 per entry), lane-parallel
        #pragma unroll
        for (int pi = 0; pi < 8; pi++) {
            int p = lane + pi * 32;
            int2 se = __ldg(&dTab.tstart[p]);
            float v = 0.0f;
            for (int t = se.x; t < se.y; t++) {
                int2 en = __ldg(&dTab.tent[t]);
                v += __int_as_float(en.y) * Sh[en.x];
            }
            ((float2*)Tw)[p] = make_float2(v, v);
        }
        __syncwarp();
        // pack x
        ull x2[16];
        x2[0] = pk2(xa0.x, xb0.x); x2[1] = pk2(xa0.y, xb0.y);
        x2[2] = pk2(xa0.z, xb0.z); x2[3] = pk2(xa0.w, xb0.w);
        x2[4] = pk2(xa1.x, xb1.x); x2[5] = pk2(xa1.y, xb1.y);
        x2[6] = pk2(xa1.z, xb1.z); x2[7] = pk2(xa1.w, xb1.w);
        x2[8] = pk2(xa2.x, xb2.x); x2[9] = pk2(xa2.y, xb2.y);
        x2[10] = pk2(xa2.z, xb2.z); x2[11] = pk2(xa2.w, xb2.w);
        x2[12] = pk2(xa3.x, xb3.x); x2[13] = pk2(xa3.y, xb3.y);
        x2[14] = pk2(xa3.z, xb3.z); x2[15] = pk2(xa3.w, xb3.w);
        // dense 16x16 contraction (f32x2)
        #pragma unroll
        for (int o = 0; o < 16; o++) {
            ull u = 0ULL;
            const ulonglong2* Trow = (const ulonglong2*)(Tw + o * 16);
            #pragma unroll
            for (int t = 0; t < 8; t++) {
                ulonglong2 tv = Trow[t];
                u = fma2(tv.x, x2[2 * t], u);
                u = fma2(tv.y, x2[2 * t + 1], u);
            }
            m2[o] = fma2(q2[lof(o)], u, m2[o]);
        }
        s = sn;
        __syncwarp();
    }

    // mp = 0.5*m ; stage for invariant contraction
    #pragma unroll
    for (int o = 0; o < 16; o++) Tw[o * 32 + lane] = mul2(m2[o], HALF2);
    __syncwarp();
    ull inv2 = Tw[lane];                         // mp[0][0]
    for (int t = 0; t < nG; t++) {
        int2 en = __ldg(&dTab.g[t]);
        unsigned m = (unsigned)en.x;
        int i32 = m & 0xFFFF, j32 = m >> 16;
        unsigned vb = (unsigned)en.y;
        ull cv2 = ((ull)vb << 32) | vb;
        inv2 = fma2(cv2, mul2(Tw[i32 + lane], Tw[j32 + lane]), inv2);
    }
    float vlo, vhi;
    upk2(inv2, vlo, vhi);
    g_inv[(size_t)a * 64 + lane] = vlo;
    g_inv[(size_t)a * 64 + 32 + lane] = vhi;
}

// ============================================================================
// MLP per atom (one warp per atom)
// ============================================================================
__global__ __launch_bounds__(128) void k_mlp(const float* __restrict__ W1,
                                             const float* __restrict__ W2,
                                             const float* __restrict__ wl,
                                             int natoms) {
    __shared__ float sW1[4096], sW2[4096], sWl[64];
    for (int i = threadIdx.x; i < 4096; i += 128) {
        sW1[i] = __ldg(W1 + i);
        sW2[i] = __ldg(W2 + i);
    }
    if (threadIdx.x < 64) sWl[threadIdx.x] = __ldg(wl + threadIdx.x);
    __syncthreads();

    int w = threadIdx.x >> 5, lane = threadIdx.x & 31;
    int a = blockIdx.x * 4 + w;
    if (a >= natoms) return;

    float i0 = g_inv[(size_t)a * 64 + lane];
    float i1 = g_inv[(size_t)a * 64 + 32 + lane];
    float h0 = 0.0f, h1 = 0.0f;
    #pragma unroll
    for (int j = 0; j < 64; j++) {
        float bj = __shfl_sync(0xffffffffu, (j < 32) ? i0 : i1, j & 31);
        h0 += bj * sW1[j * 64 + lane];
        h1 += bj * sW1[j * 64 + 32 + lane];
    }
    h0 = h0 / (1.0f + expf(-h0));
    h1 = h1 / (1.0f + expf(-h1));
    float g0 = 0.0f, g1 = 0.0f;
    #pragma unroll
    for (int j = 0; j < 64; j++) {
        float bj = __shfl_sync(0xffffffffu, (j < 32) ? h0 : h1, j & 31);
        g0 += bj * sW2[j * 64 + lane];
        g1 += bj * sW2[j * 64 + 32 + lane];
    }
    g0 = g0 / (1.0f + expf(-g0));
    g1 = g1 / (1.0f + expf(-g1));
    float p = g0 * sWl[lane] + g1 * sWl[32 + lane];
    #pragma unroll
    for (int off = 16; off; off >>= 1) p += __shfl_xor_sync(0xffffffffu, p, off);
    if (lane == 0) g_atomE[a] = p;
}

__global__ void k_reduce(float* __restrict__ out, int n) {
    __shared__ double sred[1024];
    double s = 0.0;
    for (int i = threadIdx.x; i < n; i += 1024) s += (double)g_atomE[i];
    sred[threadIdx.x] = s;
    __syncthreads();
    for (int st = 512; st; st >>= 1) {
        if (threadIdx.x < st) sred[threadIdx.x] += sred[threadIdx.x + st];
        __syncthreads();
    }
    if (threadIdx.x == 0) out[0] = (float)sred[0];
}

// ============================================================================
// Host: exact port of the reference Clebsch-Gordan / real-SH coupling tables
// ============================================================================
namespace phace_host {

using cd = std::complex<double>;

static double hfact(int n) { double r = 1; for (int i = 2; i <= n; i++) r *= i; return r; }

static double hcg(int j1, int m1, int j2, int m2, int J, int M) {
    if (m1 + m2 != M || J < std::abs(j1 - j2) || J > j1 + j2) return 0.0;
    double pref = std::sqrt((2 * J + 1) * hfact(J + j1 - j2) * hfact(J - j1 + j2) *
                            hfact(j1 + j2 - J) / hfact(j1 + j2 + J + 1));
    pref *= std::sqrt(hfact(J + M) * hfact(J - M) * hfact(j1 - m1) * hfact(j1 + m1) *
                      hfact(j2 - m2) * hfact(j2 + m2));
    double s = 0.0;
    for (int k = 0; k <= j1 + j2 - J; k++) {
        int d0 = k, d1 = j1 + j2 - J - k, d2 = j1 - m1 - k, d3 = j2 + m2 - k;
        int d4 = J - j2 + m1 + k, d5 = J - j1 - m2 + k;
        if (d0 < 0 || d1 < 0 || d2 < 0 || d3 < 0 || d4 < 0 || d5 < 0) continue;
        double den = hfact(d0) * hfact(d1) * hfact(d2) * hfact(d3) * hfact(d4) * hfact(d5);
        s += ((k & 1) ? -1.0 : 1.0) / den;
    }
    return pref * s;
}

static void hureal(int l, cd U[7][7]) {
    for (int i = 0; i < 7; i++)
        for (int j = 0; j < 7; j++) U[i][j] = cd(0.0, 0.0);
    U[l][l] = cd(1.0, 0.0);
    const double is2 = 1.0 / std::sqrt(2.0);
    for (int m = 1; m <= l; m++) {
        double sg = (m & 1) ? -1.0 : 1.0;
        U[l + m][l + m] = cd(sg * is2, 0.0);
        U[l + m][l - m] = cd(is2, 0.0);
        U[l - m][l - m] = cd(0.0, is2);
        U[l - m][l + m] = cd(0.0, -is2 * sg);
    }
}

static void hrealcg(int l1, int l2, int L, float out[7][7][7]) {
    cd U1[7][7], U2[7][7], U3[7][7];
    hureal(l1, U1); hureal(l2, U2); hureal(L, U3);
    int d1 = 2 * l1 + 1, d2 = 2 * l2 + 1, d3 = 2 * L + 1;
    static cd T[7][7][7];
    double sre = 0.0, sim = 0.0;
    for (int a = 0; a < d1; a++)
        for (int b = 0; b < d2; b++)
            for (int c = 0; c < d3; c++) {
                cd acc(0.0, 0.0);
                for (int m = 0; m < d1; m++) {
                    cd u1 = U1[a][m];
                    if (u1.real() == 0.0 && u1.imag() == 0.0) continue;
                    for (int n = 0; n < d2; n++) {
                        cd u2 = U2[b][n];
                        if (u2.real() == 0.0 && u2.imag() == 0.0) continue;
                        for (int o = 0; o < d3; o++) {
                            cd u3 = std::conj(U3[c][o]);
                            if (u3.real() == 0.0 && u3.imag() == 0.0) continue;
                            double cgv = hcg(l1, m - l1, l2, n - l2, L, o - L);
                            if (cgv != 0.0) acc += u1 * u2 * u3 * cgv;
                        }
                    }
                }
                T[a][b][c] = acc;
                sre += std::abs(acc.real());
                sim += std::abs(acc.imag());
            }
    bool usere = (sre >= sim);
    for (int a = 0; a < d1; a++)
        for (int b = 0; b < d2; b++)
            for (int c = 0; c < d3; c++)
                out[a][b][c] = (float)(usere ? T[a][b][c].real() : T[a][b][c].imag());
}

static int f2i(float v) { int r; std::memcpy(&r, &v, 4); return r; }
static unsigned long long fdup(float v) {
    unsigned u; std::memcpy(&u, &v, 4);
    return ((unsigned long long)u << 32) | u;
}

static void build_tables(Tables& H) {
    const int OFF[4] = {0, 1, 4, 9};
    struct E2 { short a; float v; };
    std::vector<E2> tp[256];
    // dense double accumulation of the full 16x16x16 coupling for the bilinear
    static double D[16][16][16];           // [o][i][j]
    std::memset(D, 0, sizeof(D));
    static float C[7][7][7];
    for (int l1 = 0; l1 < 4; l1++)
        for (int l2 = 0; l2 < 4; l2++) {
            int Llo = std::abs(l1 - l2), Lhi = std::min(l1 + l2, 3);
            for (int L = Llo; L <= Lhi; L++) {
                hrealcg(l1, l2, L, C);
                for (int a = 0; a < 2 * l1 + 1; a++)
                    for (int b = 0; b < 2 * l2 + 1; b++)
                        for (int c = 0; c < 2 * L + 1; c++) {
                            float v = C[a][b][c];
                            if (v == 0.0f) continue;
                            int o = OFF[L] + c, si = OFF[l2] + b, sa = OFF[l1] + a;
                            D[o][sa][si] += (double)v;
                            if (std::fabs(v) >= 1e-7f)
                                tp[o * 16 + si].push_back({(short)sa, v});
                        }
            }
        }
    // self-interaction: symmetric merge i<=j  (f_i f_j == f_j f_i)
    int idx = 0;
    for (int o = 0; o < 16; o++) {
        H.cs_start[o] = idx;
        for (int i = 0; i < 16; i++)
            for (int j = i; j < 16; j++) {
                double mv = (i == j) ? D[o][i][i] : (D[o][i][j] + D[o][j][i]);
                if (std::fabs(mv) < 1e-9) continue;
                if (idx >= MAXNZ) continue;
                H.self[idx].x = (unsigned long long)((i * 32) | ((j * 32) << 16));
                H.self[idx].y = fdup((float)mv);
                idx++;
            }
    }
    H.cs_start[16] = idx; H.ncs = idx;
    // T table (unchanged layout)
    idx = 0;
    for (int p = 0; p < 256; p++) {
        H.tstart[p].x = idx;
        for (auto& e : tp[p]) {
            if (idx >= MAXNZ) break;
            H.tent[idx].x = e.a;
            H.tent[idx].y = f2i(e.v);
            idx++;
        }
        H.tstart[p].y = idx;
    }
    H.nct = idx;
    // invariant table: o==0 slice, symmetric merge
    H.ng = 0;
    for (int i = 0; i < 16; i++)
        for (int j = i; j < 16; j++) {
            double mv = (i == j) ? D[0][i][i] : (D[0][i][j] + D[0][j][i]);
            if (std::fabs(mv) < 1e-9) continue;
            if (H.ng >= MAXG) continue;
            H.g[H.ng].x = (i * 32) | ((j * 32) << 16);
            H.g[H.ng].y = f2i((float)mv);
            H.ng++;
        }
}

} // namespace phace_host

// ============================================================================
// kernel_launch
// ============================================================================
extern "C" void kernel_launch(void* const* d_in, const int* in_sizes, int n_in,
                              void* d_out, int out_size) {
    const float* pos     = (const float*)d_in[0];
    const float* emb     = (const float*)d_in[1];
    const float* Winv    = (const float*)d_in[2];
    const float* Weq     = (const float*)d_in[3];
    const float* W1      = (const float*)d_in[4];
    const float* W2      = (const float*)d_in[5];
    const float* wl      = (const float*)d_in[6];
    const int*   species = (const int*)d_in[7];
    const int*   snd     = (const int*)d_in[8];
    const int*   rcv     = (const int*)d_in[9];
    int N = in_sizes[7];
    int E = in_sizes[8];
    if (N > MAXN_AT) N = MAXN_AT;
    if (E > MAXE_ED) E = MAXE_ED;

    static Tables H;                   // static: source must persist for graph replays
    phace_host::build_tables(H);       // deterministic, rebuilt every call

    // single consolidated upload (one memcpy node)
    cudaMemcpyToSymbolAsync(dTab, &H, sizeof(Tables), 0, cudaMemcpyHostToDevice, 0);

    // zero per-receiver counts via memset node (graph-legal; precedes k_count)
    void* cntPtr = nullptr;
    cudaGetSymbolAddress(&cntPtr, g_count);
    cudaMemsetAsync(cntPtr, 0, (size_t)N * sizeof(int), 0);

    int G = ((E > N ? E : N) + 255) / 256;
    k_count<<<G, 256>>>(pos, snd, rcv, species, emb, E, N);
    k_scan<<<1, 1024>>>(N);
    k_scatter<<<(E + 255) / 256, 256>>>(pos, snd, rcv, E);
    k_phaseA<<<(N + 3) / 4, 128>>>(Winv, N);
    k_phaseB<<<(N + 3) / 4, 128>>>(Weq, N, H.ng);
    k_mlp<<<(N + 3) / 4, 128>>>(W1, W2, wl, N);
    k_reduce<<<1, 1024>>>((float*)d_out, N);
}